// round 3
// baseline (speedup 1.0000x reference)
#include <cuda_runtime.h>

#define N_NODES 100000
#define IN_C 128
#define HID_C 128
#define OUT_C 64

// Scratch (device globals: no allocation allowed in kernel_launch)
__device__ float g_deg[N_NODES];
__device__ float g_dinv[N_NODES];
__device__ float g_H  [(size_t)N_NODES * HID_C];   // layer-1 pre-agg features h = xW1 (then relu'd h1)
__device__ float g_AGG[(size_t)N_NODES * HID_C];   // layer-1 accumulator
__device__ float g_H2 [(size_t)N_NODES * OUT_C];   // layer-2 pre-agg features h2 = h1 W2

// ---------------------------------------------------------------------------
// degree: deg[c] += 1 per edge (col endpoint). edge_index is int32 (JAX x64 off).
// ---------------------------------------------------------------------------
__global__ void degree_kernel(const int* __restrict__ col, int E) {
    int i = blockIdx.x * blockDim.x + threadIdx.x;
    if (i < E) {
        atomicAdd(&g_deg[col[i]], 1.0f);
    }
}

__global__ void dinv_kernel() {
    int v = blockIdx.x * blockDim.x + threadIdx.x;
    if (v < N_NODES) {
        g_dinv[v] = rsqrtf(g_deg[v] + 1.0f);
    }
}

// ---------------------------------------------------------------------------
// Tiled SGEMM with fused epilogue:
//   H[r][c]   = (A @ W)[r][c]
//   AGG[r][c] = H[r][c] * dinv[r]^2 + bias[c]     (self-loop + bias init)
// A is [M,128] row-major, W is [128,BN] row-major. BN == full output width.
// Block: 256 threads (16x16), BM=64 rows, full BN cols, TM=4, TN=BN/16.
// ---------------------------------------------------------------------------
template <int BN>
__global__ void gemm_epi_kernel(const float* __restrict__ A,
                                const float* __restrict__ W,
                                const float* __restrict__ bias,
                                float* __restrict__ H,
                                float* __restrict__ AGG,
                                int M) {
    constexpr int BM = 64;
    constexpr int BK = 16;
    constexpr int TM = 4;
    constexpr int TN = BN / 16;

    __shared__ float As[BK][BM + 1];   // transposed A tile, padded
    __shared__ float Bs[BK][BN];

    const int tid = threadIdx.x;          // 0..255
    const int tx = tid % 16;
    const int ty = tid / 16;
    const int row0 = blockIdx.x * BM;

    float acc[TM][TN];
#pragma unroll
    for (int i = 0; i < TM; i++)
#pragma unroll
        for (int j = 0; j < TN; j++) acc[i][j] = 0.0f;

    // A-load mapping: each thread loads one float4 per K-step
    const int a_row = tid >> 2;           // 0..63
    const int a_k4  = (tid & 3) * 4;      // 0,4,8,12
    const int gr_a  = row0 + a_row;

    for (int k0 = 0; k0 < 128; k0 += BK) {
        // load A tile (guard M tail)
        float4 av = make_float4(0.f, 0.f, 0.f, 0.f);
        if (gr_a < M) {
            av = *(const float4*)(A + (size_t)gr_a * 128 + k0 + a_k4);
        }
        As[a_k4 + 0][a_row] = av.x;
        As[a_k4 + 1][a_row] = av.y;
        As[a_k4 + 2][a_row] = av.z;
        As[a_k4 + 3][a_row] = av.w;

        // load B tile: BK*BN/4 float4s
        constexpr int BF4 = BK * BN / 4;
#pragma unroll
        for (int f = tid; f < BF4; f += 256) {
            int bk = f / (BN / 4);
            int bc = f % (BN / 4);
            ((float4*)Bs[bk])[bc] =
                *(const float4*)(W + (size_t)(k0 + bk) * BN + bc * 4);
        }
        __syncthreads();

#pragma unroll
        for (int k = 0; k < BK; k++) {
            float a[TM], b[TN];
#pragma unroll
            for (int i = 0; i < TM; i++) a[i] = As[k][ty * TM + i];
#pragma unroll
            for (int j = 0; j < TN; j += 4) {
                float4 bv = ((const float4*)Bs[k])[(tx * TN + j) / 4];
                b[j + 0] = bv.x; b[j + 1] = bv.y; b[j + 2] = bv.z; b[j + 3] = bv.w;
            }
#pragma unroll
            for (int i = 0; i < TM; i++)
#pragma unroll
                for (int j = 0; j < TN; j++)
                    acc[i][j] = fmaf(a[i], b[j], acc[i][j]);
        }
        __syncthreads();
    }

    // epilogue
#pragma unroll
    for (int i = 0; i < TM; i++) {
        int r = row0 + ty * TM + i;
        if (r < M) {
            float di = g_dinv[r];
            float d2 = di * di;
#pragma unroll
            for (int j = 0; j < TN; j++) {
                int c = tx * TN + j;
                float h = acc[i][j];
                H[(size_t)r * BN + c]   = h;
                AGG[(size_t)r * BN + c] = fmaf(h, d2, bias[c]);
            }
        }
    }
}

// ---------------------------------------------------------------------------
// Edge scatter: AGG[col] += dinv[row]*dinv[col] * H[row]
// One (sub-)warp slice per edge; lane handles one float4 of the feature row.
// ---------------------------------------------------------------------------
template <int COLS>
__global__ void scatter_kernel(const int* __restrict__ rowp,
                               const int* __restrict__ colp,
                               const float* __restrict__ H,
                               float* __restrict__ AGG,
                               int E) {
    constexpr int LPE = COLS / 4;     // lanes per edge (32 or 16)
    constexpr int EPW = 32 / LPE;     // edges per warp per step (1 or 2)

    const int lane = threadIdx.x & 31;
    const int warp = (blockIdx.x * blockDim.x + threadIdx.x) >> 5;
    const int nwarps = (gridDim.x * blockDim.x) >> 5;
    const int sub = lane / LPE;
    const int l   = lane % LPE;

    for (long long e = (long long)warp * EPW + sub; e < E;
         e += (long long)nwarps * EPW) {
        int r = rowp[e];
        int c = colp[e];
        float nrm = g_dinv[r] * g_dinv[c];
        float4 v = *(const float4*)(H + (size_t)r * COLS + l * 4);
        float* dst = AGG + (size_t)c * COLS + l * 4;
        atomicAdd(dst + 0, v.x * nrm);
        atomicAdd(dst + 1, v.y * nrm);
        atomicAdd(dst + 2, v.z * nrm);
        atomicAdd(dst + 3, v.w * nrm);
    }
}

// ---------------------------------------------------------------------------
// relu: H = max(AGG, 0)  (vectorized, into H buffer = layer-2 input)
// ---------------------------------------------------------------------------
__global__ void relu_kernel(int n4) {
    int i = blockIdx.x * blockDim.x + threadIdx.x;
    if (i < n4) {
        float4 v = ((const float4*)g_AGG)[i];
        v.x = fmaxf(v.x, 0.f);
        v.y = fmaxf(v.y, 0.f);
        v.z = fmaxf(v.z, 0.f);
        v.w = fmaxf(v.w, 0.f);
        ((float4*)g_H)[i] = v;
    }
}

// ---------------------------------------------------------------------------
// launch
// ---------------------------------------------------------------------------
extern "C" void kernel_launch(void* const* d_in, const int* in_sizes, int n_in,
                              void* d_out, int out_size) {
    const float* x  = (const float*)d_in[0];
    const int*   ei = (const int*)d_in[1];      // int32: JAX x64-disabled downcasts int64
    const float* W1 = (const float*)d_in[2];
    const float* b1 = (const float*)d_in[3];
    const float* W2 = (const float*)d_in[4];
    const float* b2 = (const float*)d_in[5];
    float*       out = (float*)d_out;

    const int E = in_sizes[1] / 2;
    const int* rowp = ei;        // edge_index[0]
    const int* colp = ei + E;    // edge_index[1]

    float *deg, *H, *AGG, *H2;
    cudaGetSymbolAddress((void**)&deg, g_deg);
    cudaGetSymbolAddress((void**)&H,   g_H);
    cudaGetSymbolAddress((void**)&AGG, g_AGG);
    cudaGetSymbolAddress((void**)&H2,  g_H2);

    // 1. degrees + dinv
    cudaMemsetAsync(deg, 0, N_NODES * sizeof(float));
    degree_kernel<<<(E + 255) / 256, 256>>>(colp, E);
    dinv_kernel<<<(N_NODES + 255) / 256, 256>>>();

    // 2. layer 1: h = x@W1; AGG init = h*dinv^2 + b1
    gemm_epi_kernel<HID_C><<<(N_NODES + 63) / 64, 256>>>(x, W1, b1, H, AGG, N_NODES);

    // 3. layer 1 scatter
    scatter_kernel<HID_C><<<148 * 8, 256>>>(rowp, colp, H, AGG, E);

    // 4. relu into H (becomes layer-2 input)
    relu_kernel<<<(N_NODES * HID_C / 4 + 255) / 256, 256>>>(N_NODES * HID_C / 4);

    // 5. layer 2: h2 = h1@W2; d_out init = h2*dinv^2 + b2
    gemm_epi_kernel<OUT_C><<<(N_NODES + 63) / 64, 256>>>(H, W2, b2, H2, out, N_NODES);

    // 6. layer 2 scatter straight into d_out
    scatter_kernel<OUT_C><<<148 * 8, 256>>>(rowp, colp, H2, out, E);
}

// round 5
// speedup vs baseline: 1.8505x; 1.8505x over previous
#include <cuda_runtime.h>

#define N_NODES 100000
#define IN_C 128
#define HID_C 128
#define OUT_C 64

// Scratch (device globals: no allocation allowed in kernel_launch)
__device__ float g_deg[N_NODES];
__device__ float g_dinv[N_NODES];
__device__ float g_H  [(size_t)N_NODES * HID_C];   // layer-1 pre-agg features h = xW1 (then relu'd h1)
__device__ float g_AGG[(size_t)N_NODES * HID_C];   // layer-1 accumulator
__device__ float g_H2 [(size_t)N_NODES * OUT_C];   // layer-2 pre-agg features h2 = h1 W2

// Vector reduction: one RED.128 instead of 4 scalar ATOMG (sm_90+)
__device__ __forceinline__ void red_add_v4(float* p, float a, float b, float c, float d) {
    asm volatile("red.global.add.v4.f32 [%0], {%1, %2, %3, %4};"
                 :: "l"(p), "f"(a), "f"(b), "f"(c), "f"(d) : "memory");
}

__device__ __forceinline__ void red_add_f32(float* p, float v) {
    asm volatile("red.global.add.f32 [%0], %1;" :: "l"(p), "f"(v) : "memory");
}

// ---------------------------------------------------------------------------
// degree: deg[c] += 1 per edge (col endpoint). edge_index is int32 (JAX x64 off).
// ---------------------------------------------------------------------------
__global__ void degree_kernel(const int* __restrict__ col, int E) {
    int i = blockIdx.x * blockDim.x + threadIdx.x;
    if (i < E) {
        red_add_f32(&g_deg[col[i]], 1.0f);
    }
}

__global__ void dinv_kernel() {
    int v = blockIdx.x * blockDim.x + threadIdx.x;
    if (v < N_NODES) {
        g_dinv[v] = rsqrtf(g_deg[v] + 1.0f);
    }
}

// ---------------------------------------------------------------------------
// Tiled SGEMM with fused epilogue:
//   H[r][c]   = (A @ W)[r][c]
//   AGG[r][c] = H[r][c] * dinv[r]^2 + bias[c]     (self-loop + bias init)
// ---------------------------------------------------------------------------
template <int BN>
__global__ void gemm_epi_kernel(const float* __restrict__ A,
                                const float* __restrict__ W,
                                const float* __restrict__ bias,
                                float* __restrict__ H,
                                float* __restrict__ AGG,
                                int M) {
    constexpr int BM = 64;
    constexpr int BK = 16;
    constexpr int TM = 4;
    constexpr int TN = BN / 16;

    __shared__ float As[BK][BM + 1];   // transposed A tile, padded
    __shared__ float Bs[BK][BN];

    const int tid = threadIdx.x;          // 0..255
    const int tx = tid % 16;
    const int ty = tid / 16;
    const int row0 = blockIdx.x * BM;

    float acc[TM][TN];
#pragma unroll
    for (int i = 0; i < TM; i++)
#pragma unroll
        for (int j = 0; j < TN; j++) acc[i][j] = 0.0f;

    const int a_row = tid >> 2;           // 0..63
    const int a_k4  = (tid & 3) * 4;      // 0,4,8,12
    const int gr_a  = row0 + a_row;

    for (int k0 = 0; k0 < 128; k0 += BK) {
        float4 av = make_float4(0.f, 0.f, 0.f, 0.f);
        if (gr_a < M) {
            av = *(const float4*)(A + (size_t)gr_a * 128 + k0 + a_k4);
        }
        As[a_k4 + 0][a_row] = av.x;
        As[a_k4 + 1][a_row] = av.y;
        As[a_k4 + 2][a_row] = av.z;
        As[a_k4 + 3][a_row] = av.w;

        constexpr int BF4 = BK * BN / 4;
#pragma unroll
        for (int f = tid; f < BF4; f += 256) {
            int bk = f / (BN / 4);
            int bc = f % (BN / 4);
            ((float4*)Bs[bk])[bc] =
                *(const float4*)(W + (size_t)(k0 + bk) * BN + bc * 4);
        }
        __syncthreads();

#pragma unroll
        for (int k = 0; k < BK; k++) {
            float a[TM], b[TN];
#pragma unroll
            for (int i = 0; i < TM; i++) a[i] = As[k][ty * TM + i];
#pragma unroll
            for (int j = 0; j < TN; j += 4) {
                float4 bv = ((const float4*)Bs[k])[(tx * TN + j) / 4];
                b[j + 0] = bv.x; b[j + 1] = bv.y; b[j + 2] = bv.z; b[j + 3] = bv.w;
            }
#pragma unroll
            for (int i = 0; i < TM; i++)
#pragma unroll
                for (int j = 0; j < TN; j++)
                    acc[i][j] = fmaf(a[i], b[j], acc[i][j]);
        }
        __syncthreads();
    }

#pragma unroll
    for (int i = 0; i < TM; i++) {
        int r = row0 + ty * TM + i;
        if (r < M) {
            float di = g_dinv[r];
            float d2 = di * di;
#pragma unroll
            for (int j = 0; j < TN; j++) {
                int c = tx * TN + j;
                float h = acc[i][j];
                H[(size_t)r * BN + c]   = h;
                AGG[(size_t)r * BN + c] = fmaf(h, d2, bias[c]);
            }
        }
    }
}

// ---------------------------------------------------------------------------
// Edge scatter: AGG[col] += dinv[row]*dinv[col] * H[row]
// One (sub-)warp slice per edge; lane handles one float4 via RED.128.
// ---------------------------------------------------------------------------
template <int COLS>
__global__ void scatter_kernel(const int* __restrict__ rowp,
                               const int* __restrict__ colp,
                               const float* __restrict__ H,
                               float* __restrict__ AGG,
                               int E) {
    constexpr int LPE = COLS / 4;     // lanes per edge (32 or 16)
    constexpr int EPW = 32 / LPE;     // edges per warp per step (1 or 2)

    const int lane = threadIdx.x & 31;
    const int warp = (blockIdx.x * blockDim.x + threadIdx.x) >> 5;
    const int nwarps = (gridDim.x * blockDim.x) >> 5;
    const int sub = lane / LPE;
    const int l   = lane % LPE;

    for (long long e = (long long)warp * EPW + sub; e < E;
         e += (long long)nwarps * EPW) {
        int r = rowp[e];
        int c = colp[e];
        float nrm = g_dinv[r] * g_dinv[c];
        float4 v = *(const float4*)(H + (size_t)r * COLS + l * 4);
        float* dst = AGG + (size_t)c * COLS + l * 4;
        red_add_v4(dst, v.x * nrm, v.y * nrm, v.z * nrm, v.w * nrm);
    }
}

// ---------------------------------------------------------------------------
// relu: H = max(AGG, 0)  (vectorized, into H buffer = layer-2 input)
// ---------------------------------------------------------------------------
__global__ void relu_kernel(int n4) {
    int i = blockIdx.x * blockDim.x + threadIdx.x;
    if (i < n4) {
        float4 v = ((const float4*)g_AGG)[i];
        v.x = fmaxf(v.x, 0.f);
        v.y = fmaxf(v.y, 0.f);
        v.z = fmaxf(v.z, 0.f);
        v.w = fmaxf(v.w, 0.f);
        ((float4*)g_H)[i] = v;
    }
}

// ---------------------------------------------------------------------------
// launch
// ---------------------------------------------------------------------------
extern "C" void kernel_launch(void* const* d_in, const int* in_sizes, int n_in,
                              void* d_out, int out_size) {
    const float* x  = (const float*)d_in[0];
    const int*   ei = (const int*)d_in[1];      // int32 (JAX x64 disabled)
    const float* W1 = (const float*)d_in[2];
    const float* b1 = (const float*)d_in[3];
    const float* W2 = (const float*)d_in[4];
    const float* b2 = (const float*)d_in[5];
    float*       out = (float*)d_out;

    const int E = in_sizes[1] / 2;
    const int* rowp = ei;        // edge_index[0]
    const int* colp = ei + E;    // edge_index[1]

    float *deg, *H, *AGG, *H2;
    cudaGetSymbolAddress((void**)&deg, g_deg);
    cudaGetSymbolAddress((void**)&H,   g_H);
    cudaGetSymbolAddress((void**)&AGG, g_AGG);
    cudaGetSymbolAddress((void**)&H2,  g_H2);

    // 1. degrees + dinv
    cudaMemsetAsync(deg, 0, N_NODES * sizeof(float));
    degree_kernel<<<(E + 255) / 256, 256>>>(colp, E);
    dinv_kernel<<<(N_NODES + 255) / 256, 256>>>();

    // 2. layer 1: h = x@W1; AGG init = h*dinv^2 + b1
    gemm_epi_kernel<HID_C><<<(N_NODES + 63) / 64, 256>>>(x, W1, b1, H, AGG, N_NODES);

    // 3. layer 1 scatter
    scatter_kernel<HID_C><<<148 * 8, 256>>>(rowp, colp, H, AGG, E);

    // 4. relu into H (becomes layer-2 input)
    relu_kernel<<<(N_NODES * HID_C / 4 + 255) / 256, 256>>>(N_NODES * HID_C / 4);

    // 5. layer 2: h2 = h1@W2; d_out init = h2*dinv^2 + b2
    gemm_epi_kernel<OUT_C><<<(N_NODES + 63) / 64, 256>>>(H, W2, b2, H2, out, N_NODES);

    // 6. layer 2 scatter straight into d_out
    scatter_kernel<OUT_C><<<148 * 8, 256>>>(rowp, colp, H2, out, E);
}

// round 10
// speedup vs baseline: 2.3993x; 1.2966x over previous
#include <cuda_runtime.h>

#define N_NODES 100000
#define IN_C 128
#define HID_C 128
#define OUT_C 64
#define MAX_E 1600000
#define NB ((N_NODES + 255) / 256)

// Scratch (device globals: no allocation allowed in kernel_launch)
__device__ int   g_cnt [N_NODES];    // in-degree (by col)
__device__ int   g_fill[N_NODES];    // bucket fill cursors
__device__ int   g_off [N_NODES];    // CSR offsets (exclusive scan of cnt)
__device__ int   g_bsum[NB];         // per-block sums for scan
__device__ int   g_csr [MAX_E];      // CSR: source node (row) per edge, bucketed by col
__device__ float g_dinv[N_NODES];
__device__ float g_H  [(size_t)N_NODES * HID_C];   // layer-1 pre-agg h = xW1 (then relu'd)
__device__ float g_AGG[(size_t)N_NODES * HID_C];   // layer-1 accumulator
__device__ float g_H2 [(size_t)N_NODES * OUT_C];   // layer-2 pre-agg h2 = h1 W2

// ---------------------------------------------------------------------------
// CSR construction
// ---------------------------------------------------------------------------
__global__ void count_kernel(const int* __restrict__ col, int E) {
    int i = blockIdx.x * blockDim.x + threadIdx.x;
    if (i < E) {
        asm volatile("red.global.add.s32 [%0], %1;"
                     :: "l"(&g_cnt[col[i]]), "r"(1) : "memory");
    }
}

__global__ void dinv_kernel() {
    int v = blockIdx.x * blockDim.x + threadIdx.x;
    if (v < N_NODES) {
        g_dinv[v] = rsqrtf((float)g_cnt[v] + 1.0f);
    }
}

__global__ void block_sums_kernel() {
    __shared__ int sh[256];
    int v = blockIdx.x * 256 + threadIdx.x;
    sh[threadIdx.x] = (v < N_NODES) ? g_cnt[v] : 0;
    __syncthreads();
#pragma unroll
    for (int d = 128; d > 0; d >>= 1) {
        if (threadIdx.x < d) sh[threadIdx.x] += sh[threadIdx.x + d];
        __syncthreads();
    }
    if (threadIdx.x == 0) g_bsum[blockIdx.x] = sh[0];
}

__global__ void scan_bsums_kernel() {
    if (threadIdx.x == 0 && blockIdx.x == 0) {
        int acc = 0;
        for (int i = 0; i < NB; i++) {
            int t = g_bsum[i];
            g_bsum[i] = acc;
            acc += t;
        }
    }
}

__global__ void scan_block_kernel() {
    __shared__ int sh[256];
    int v = blockIdx.x * 256 + threadIdx.x;
    int x = (v < N_NODES) ? g_cnt[v] : 0;
    sh[threadIdx.x] = x;
    __syncthreads();
#pragma unroll
    for (int d = 1; d < 256; d <<= 1) {
        int t = (threadIdx.x >= d) ? sh[threadIdx.x - d] : 0;
        __syncthreads();
        sh[threadIdx.x] += t;
        __syncthreads();
    }
    if (v < N_NODES) g_off[v] = g_bsum[blockIdx.x] + sh[threadIdx.x] - x;
}

__global__ void fill_csr_kernel(const int* __restrict__ rowp,
                                const int* __restrict__ colp, int E) {
    int i = blockIdx.x * blockDim.x + threadIdx.x;
    if (i < E) {
        int c = colp[i];
        int p = g_off[c] + atomicAdd(&g_fill[c], 1);
        g_csr[p] = rowp[i];
    }
}

// ---------------------------------------------------------------------------
// Tiled SGEMM with fused epilogue:
//   H[r][c]   = (A @ W)[r][c]
//   AGG[r][c] = H[r][c] * dinv[r]^2 + bias[c]     (self-loop + bias init)
// ---------------------------------------------------------------------------
template <int BN>
__global__ void gemm_epi_kernel(const float* __restrict__ A,
                                const float* __restrict__ W,
                                const float* __restrict__ bias,
                                float* __restrict__ H,
                                float* __restrict__ AGG,
                                int M) {
    constexpr int BM = 64;
    constexpr int BK = 16;
    constexpr int TM = 4;
    constexpr int TN = BN / 16;

    __shared__ float As[BK][BM + 1];
    __shared__ float Bs[BK][BN];

    const int tid = threadIdx.x;
    const int tx = tid % 16;
    const int ty = tid / 16;
    const int row0 = blockIdx.x * BM;

    float acc[TM][TN];
#pragma unroll
    for (int i = 0; i < TM; i++)
#pragma unroll
        for (int j = 0; j < TN; j++) acc[i][j] = 0.0f;

    const int a_row = tid >> 2;
    const int a_k4  = (tid & 3) * 4;
    const int gr_a  = row0 + a_row;

    for (int k0 = 0; k0 < 128; k0 += BK) {
        float4 av = make_float4(0.f, 0.f, 0.f, 0.f);
        if (gr_a < M) {
            av = *(const float4*)(A + (size_t)gr_a * 128 + k0 + a_k4);
        }
        As[a_k4 + 0][a_row] = av.x;
        As[a_k4 + 1][a_row] = av.y;
        As[a_k4 + 2][a_row] = av.z;
        As[a_k4 + 3][a_row] = av.w;

        constexpr int BF4 = BK * BN / 4;
#pragma unroll
        for (int f = tid; f < BF4; f += 256) {
            int bk = f / (BN / 4);
            int bc = f % (BN / 4);
            ((float4*)Bs[bk])[bc] =
                *(const float4*)(W + (size_t)(k0 + bk) * BN + bc * 4);
        }
        __syncthreads();

#pragma unroll
        for (int k = 0; k < BK; k++) {
            float a[TM], b[TN];
#pragma unroll
            for (int i = 0; i < TM; i++) a[i] = As[k][ty * TM + i];
#pragma unroll
            for (int j = 0; j < TN; j += 4) {
                float4 bv = ((const float4*)Bs[k])[(tx * TN + j) / 4];
                b[j + 0] = bv.x; b[j + 1] = bv.y; b[j + 2] = bv.z; b[j + 3] = bv.w;
            }
#pragma unroll
            for (int i = 0; i < TM; i++)
#pragma unroll
                for (int j = 0; j < TN; j++)
                    acc[i][j] = fmaf(a[i], b[j], acc[i][j]);
        }
        __syncthreads();
    }

#pragma unroll
    for (int i = 0; i < TM; i++) {
        int r = row0 + ty * TM + i;
        if (r < M) {
            float di = g_dinv[r];
            float d2 = di * di;
#pragma unroll
            for (int j = 0; j < TN; j++) {
                int c = tx * TN + j;
                float h = acc[i][j];
                H[(size_t)r * BN + c]   = h;
                AGG[(size_t)r * BN + c] = fmaf(h, d2, bias[c]);
            }
        }
    }
}

// ---------------------------------------------------------------------------
// CSR gather: AGG[v] += dinv[v] * sum_{r in nbr(v)} dinv[r] * H[r]
// One (sub-)warp per node, lane handles one float4 of the feature row.
// No atomics: single writer per destination row.
// ---------------------------------------------------------------------------
template <int COLS>
__global__ void gather_kernel(const float* __restrict__ H,
                              float* __restrict__ AGG) {
    constexpr int LPE = COLS / 4;     // lanes per node (32 or 16)
    constexpr int NPW = 32 / LPE;     // nodes per warp (1 or 2)

    const int lane = threadIdx.x & 31;
    const int warp = (blockIdx.x * blockDim.x + threadIdx.x) >> 5;
    const int sub = lane / LPE;
    const int l   = lane % LPE;

    const int v = warp * NPW + sub;
    if (v >= N_NODES) return;

    const int beg = g_off[v];
    const int n   = g_cnt[v];
    const int* __restrict__ nbr = g_csr + beg;

    float4 acc = make_float4(0.f, 0.f, 0.f, 0.f);

    int e = 0;
    for (; e + 4 <= n; e += 4) {
        int r0 = nbr[e + 0], r1 = nbr[e + 1], r2 = nbr[e + 2], r3 = nbr[e + 3];
        float w0 = g_dinv[r0], w1 = g_dinv[r1], w2 = g_dinv[r2], w3 = g_dinv[r3];
        float4 v0 = *(const float4*)(H + (size_t)r0 * COLS + l * 4);
        float4 v1 = *(const float4*)(H + (size_t)r1 * COLS + l * 4);
        float4 v2 = *(const float4*)(H + (size_t)r2 * COLS + l * 4);
        float4 v3 = *(const float4*)(H + (size_t)r3 * COLS + l * 4);
        acc.x = fmaf(w0, v0.x, acc.x); acc.y = fmaf(w0, v0.y, acc.y);
        acc.z = fmaf(w0, v0.z, acc.z); acc.w = fmaf(w0, v0.w, acc.w);
        acc.x = fmaf(w1, v1.x, acc.x); acc.y = fmaf(w1, v1.y, acc.y);
        acc.z = fmaf(w1, v1.z, acc.z); acc.w = fmaf(w1, v1.w, acc.w);
        acc.x = fmaf(w2, v2.x, acc.x); acc.y = fmaf(w2, v2.y, acc.y);
        acc.z = fmaf(w2, v2.z, acc.z); acc.w = fmaf(w2, v2.w, acc.w);
        acc.x = fmaf(w3, v3.x, acc.x); acc.y = fmaf(w3, v3.y, acc.y);
        acc.z = fmaf(w3, v3.z, acc.z); acc.w = fmaf(w3, v3.w, acc.w);
    }
    for (; e < n; e++) {
        int r = nbr[e];
        float w = g_dinv[r];
        float4 hv = *(const float4*)(H + (size_t)r * COLS + l * 4);
        acc.x = fmaf(w, hv.x, acc.x); acc.y = fmaf(w, hv.y, acc.y);
        acc.z = fmaf(w, hv.z, acc.z); acc.w = fmaf(w, hv.w, acc.w);
    }

    float dv = g_dinv[v];
    float* dst = AGG + (size_t)v * COLS + l * 4;
    float4 o = *(const float4*)dst;
    o.x = fmaf(dv, acc.x, o.x);
    o.y = fmaf(dv, acc.y, o.y);
    o.z = fmaf(dv, acc.z, o.z);
    o.w = fmaf(dv, acc.w, o.w);
    *(float4*)dst = o;
}

// ---------------------------------------------------------------------------
// relu: H = max(AGG, 0)  (vectorized, into H buffer = layer-2 input)
// ---------------------------------------------------------------------------
__global__ void relu_kernel(int n4) {
    int i = blockIdx.x * blockDim.x + threadIdx.x;
    if (i < n4) {
        float4 v = ((const float4*)g_AGG)[i];
        v.x = fmaxf(v.x, 0.f);
        v.y = fmaxf(v.y, 0.f);
        v.z = fmaxf(v.z, 0.f);
        v.w = fmaxf(v.w, 0.f);
        ((float4*)g_H)[i] = v;
    }
}

// ---------------------------------------------------------------------------
// launch
// ---------------------------------------------------------------------------
extern "C" void kernel_launch(void* const* d_in, const int* in_sizes, int n_in,
                              void* d_out, int out_size) {
    const float* x  = (const float*)d_in[0];
    const int*   ei = (const int*)d_in[1];      // int32 (JAX x64 disabled)
    const float* W1 = (const float*)d_in[2];
    const float* b1 = (const float*)d_in[3];
    const float* W2 = (const float*)d_in[4];
    const float* b2 = (const float*)d_in[5];
    float*       out = (float*)d_out;

    const int E = in_sizes[1] / 2;
    const int* rowp = ei;        // edge_index[0]
    const int* colp = ei + E;    // edge_index[1]

    float *H, *AGG, *H2;
    int *cnt, *fill;
    cudaGetSymbolAddress((void**)&H,    g_H);
    cudaGetSymbolAddress((void**)&AGG,  g_AGG);
    cudaGetSymbolAddress((void**)&H2,   g_H2);
    cudaGetSymbolAddress((void**)&cnt,  g_cnt);
    cudaGetSymbolAddress((void**)&fill, g_fill);

    // 1. CSR build: counts, dinv, offsets (scan), fill
    cudaMemsetAsync(cnt,  0, N_NODES * sizeof(int));
    cudaMemsetAsync(fill, 0, N_NODES * sizeof(int));
    count_kernel<<<(E + 255) / 256, 256>>>(colp, E);
    dinv_kernel<<<NB, 256>>>();
    block_sums_kernel<<<NB, 256>>>();
    scan_bsums_kernel<<<1, 32>>>();
    scan_block_kernel<<<NB, 256>>>();
    fill_csr_kernel<<<(E + 255) / 256, 256>>>(rowp, colp, E);

    // 2. layer 1: h = x@W1; AGG init = h*dinv^2 + b1
    gemm_epi_kernel<HID_C><<<(N_NODES + 63) / 64, 256>>>(x, W1, b1, H, AGG, N_NODES);

    // 3. layer 1 gather (warp per node, no atomics)
    gather_kernel<HID_C><<<(N_NODES * (HID_C / 4 / 32) * 32 + 255) / 256 + 1, 256>>>(H, AGG);

    // 4. relu into H (becomes layer-2 input)
    relu_kernel<<<(N_NODES * HID_C / 4 + 255) / 256, 256>>>(N_NODES * HID_C / 4);

    // 5. layer 2: h2 = h1@W2; d_out init = h2*dinv^2 + b2
    gemm_epi_kernel<OUT_C><<<(N_NODES + 63) / 64, 256>>>(H, W2, b2, H2, out, N_NODES);

    // 6. layer 2 gather straight into d_out (2 nodes per warp)
    gather_kernel<OUT_C><<<(N_NODES / 2 * 32 + 255) / 256 + 1, 256>>>(H2, out);
}

// round 13
// speedup vs baseline: 3.6226x; 1.5099x over previous
#include <cuda_runtime.h>

#define N_NODES 100000
#define IN_C 128
#define HID_C 128
#define OUT_C 64
#define MAX_E 1600000
#define NB ((N_NODES + 255) / 256)

// Scratch (device globals: no allocation allowed in kernel_launch)
__device__ int   g_cnt [N_NODES];    // in-degree (by col)
__device__ int   g_fill[N_NODES];    // bucket fill cursors
__device__ int   g_off [N_NODES];    // CSR offsets (exclusive scan of cnt)
__device__ int   g_bsum[NB];         // per-block sums for scan
__device__ int   g_csr [MAX_E];      // CSR: source node (row) per edge, bucketed by col
__device__ float g_dinv[N_NODES];
__device__ float g_H  [(size_t)N_NODES * HID_C];   // layer-1 pre-agg h = xW1
__device__ float g_H1R[(size_t)N_NODES * HID_C];   // layer-1 output after agg+relu
__device__ float g_H2 [(size_t)N_NODES * OUT_C];   // layer-2 pre-agg h2 = h1R W2

// ---------------------------------------------------------------------------
// CSR construction
// ---------------------------------------------------------------------------
__global__ void count_kernel(const int* __restrict__ col, int E) {
    int i = blockIdx.x * blockDim.x + threadIdx.x;
    if (i < E) {
        asm volatile("red.global.add.s32 [%0], %1;"
                     :: "l"(&g_cnt[col[i]]), "r"(1) : "memory");
    }
}

__global__ void dinv_kernel() {
    int v = blockIdx.x * blockDim.x + threadIdx.x;
    if (v < N_NODES) {
        g_dinv[v] = rsqrtf((float)g_cnt[v] + 1.0f);
    }
}

__global__ void block_sums_kernel() {
    __shared__ int sh[256];
    int v = blockIdx.x * 256 + threadIdx.x;
    sh[threadIdx.x] = (v < N_NODES) ? g_cnt[v] : 0;
    __syncthreads();
#pragma unroll
    for (int d = 128; d > 0; d >>= 1) {
        if (threadIdx.x < d) sh[threadIdx.x] += sh[threadIdx.x + d];
        __syncthreads();
    }
    if (threadIdx.x == 0) g_bsum[blockIdx.x] = sh[0];
}

// Parallel exclusive scan of the NB (=391) block sums, single 512-thread block.
__global__ void scan_bsums_kernel() {
    __shared__ int sh[512];
    int t = threadIdx.x;
    int x = (t < NB) ? g_bsum[t] : 0;
    sh[t] = x;
    __syncthreads();
#pragma unroll
    for (int d = 1; d < 512; d <<= 1) {
        int y = (t >= d) ? sh[t - d] : 0;
        __syncthreads();
        sh[t] += y;
        __syncthreads();
    }
    if (t < NB) g_bsum[t] = sh[t] - x;   // exclusive
}

__global__ void scan_block_kernel() {
    __shared__ int sh[256];
    int v = blockIdx.x * 256 + threadIdx.x;
    int x = (v < N_NODES) ? g_cnt[v] : 0;
    sh[threadIdx.x] = x;
    __syncthreads();
#pragma unroll
    for (int d = 1; d < 256; d <<= 1) {
        int t = (threadIdx.x >= d) ? sh[threadIdx.x - d] : 0;
        __syncthreads();
        sh[threadIdx.x] += t;
        __syncthreads();
    }
    if (v < N_NODES) g_off[v] = g_bsum[blockIdx.x] + sh[threadIdx.x] - x;
}

__global__ void fill_csr_kernel(const int* __restrict__ rowp,
                                const int* __restrict__ colp, int E) {
    int i = blockIdx.x * blockDim.x + threadIdx.x;
    if (i < E) {
        int c = colp[i];
        int p = g_off[c] + atomicAdd(&g_fill[c], 1);
        g_csr[p] = rowp[i];
    }
}

// ---------------------------------------------------------------------------
// SGEMM: H = A @ W.  A [M,128] row-major, W [128,BN] row-major.
// BM=128, BK=16, 256 threads (16x16), TM=8, TN=BN/16.
// As padded to BM+4=132: row stride 528B is 16B-aligned (LDS.128 legal),
// and the 4 k-groups of the transposed store alternate banks 0-7/16-23
// (only 2-way store conflicts).
// ---------------------------------------------------------------------------
template <int BN>
__global__ void gemm_kernel(const float* __restrict__ A,
                            const float* __restrict__ W,
                            float* __restrict__ H,
                            int M) {
    constexpr int BM = 128;
    constexpr int BK = 16;
    constexpr int TM = 8;
    constexpr int TN = BN / 16;

    __shared__ float As[BK][BM + 4];
    __shared__ float Bs[BK][BN];

    const int tid = threadIdx.x;
    const int tx = tid % 16;
    const int ty = tid / 16;
    const int row0 = blockIdx.x * BM;

    float acc[TM][TN];
#pragma unroll
    for (int i = 0; i < TM; i++)
#pragma unroll
        for (int j = 0; j < TN; j++) acc[i][j] = 0.0f;

    for (int k0 = 0; k0 < 128; k0 += BK) {
        // A tile: 128x16 = 512 float4s, 2 per thread, stored transposed
#pragma unroll
        for (int i = 0; i < 2; i++) {
            int f = tid + i * 256;
            int r  = f >> 2;             // 0..127
            int k4 = (f & 3) * 4;        // 0,4,8,12
            float4 av = make_float4(0.f, 0.f, 0.f, 0.f);
            if (row0 + r < M) {
                av = *(const float4*)(A + (size_t)(row0 + r) * 128 + k0 + k4);
            }
            As[k4 + 0][r] = av.x;
            As[k4 + 1][r] = av.y;
            As[k4 + 2][r] = av.z;
            As[k4 + 3][r] = av.w;
        }

        // B tile: BK x BN
        constexpr int BF4 = BK * BN / 4;
#pragma unroll
        for (int f = tid; f < BF4; f += 256) {
            int bk = f / (BN / 4);
            int bc = f % (BN / 4);
            ((float4*)Bs[bk])[bc] =
                *(const float4*)(W + (size_t)(k0 + bk) * BN + bc * 4);
        }
        __syncthreads();

#pragma unroll
        for (int k = 0; k < BK; k++) {
            float a[TM], b[TN];
#pragma unroll
            for (int i = 0; i < TM; i += 4) {
                float4 av = *(const float4*)&As[k][ty * TM + i];
                a[i + 0] = av.x; a[i + 1] = av.y; a[i + 2] = av.z; a[i + 3] = av.w;
            }
#pragma unroll
            for (int j = 0; j < TN; j += 4) {
                float4 bv = ((const float4*)Bs[k])[(tx * TN + j) / 4];
                b[j + 0] = bv.x; b[j + 1] = bv.y; b[j + 2] = bv.z; b[j + 3] = bv.w;
            }
#pragma unroll
            for (int i = 0; i < TM; i++)
#pragma unroll
                for (int j = 0; j < TN; j++)
                    acc[i][j] = fmaf(a[i], b[j], acc[i][j]);
        }
        __syncthreads();
    }

#pragma unroll
    for (int i = 0; i < TM; i++) {
        int r = row0 + ty * TM + i;
        if (r < M) {
#pragma unroll
            for (int j = 0; j < TN; j += 4) {
                float4 o = make_float4(acc[i][j], acc[i][j + 1],
                                       acc[i][j + 2], acc[i][j + 3]);
                *(float4*)(H + (size_t)r * BN + tx * TN + j) = o;
            }
        }
    }
}

// ---------------------------------------------------------------------------
// CSR gather with fused GCN epilogue:
//   dst[v] = act( dinv[v] * sum_{r in nbr(v)} dinv[r]*H[r]
//                 + dinv[v]^2 * H[v] + bias )
// One (sub-)warp per node, lane handles one float4. No atomics.
// ---------------------------------------------------------------------------
template <int COLS, bool RELU>
__global__ void gather_kernel(const float* __restrict__ H,
                              const float* __restrict__ bias,
                              float* __restrict__ dst) {
    constexpr int LPE = COLS / 4;     // lanes per node (32 or 16)
    constexpr int NPW = 32 / LPE;     // nodes per warp (1 or 2)

    const int lane = threadIdx.x & 31;
    const int warp = (blockIdx.x * blockDim.x + threadIdx.x) >> 5;
    const int sub = lane / LPE;
    const int l   = lane % LPE;

    const int v = warp * NPW + sub;
    if (v >= N_NODES) return;

    const int beg = g_off[v];
    const int n   = g_cnt[v];
    const int* __restrict__ nbr = g_csr + beg;

    float4 acc = make_float4(0.f, 0.f, 0.f, 0.f);

    int e = 0;
    for (; e + 4 <= n; e += 4) {
        int r0 = nbr[e + 0], r1 = nbr[e + 1], r2 = nbr[e + 2], r3 = nbr[e + 3];
        float w0 = g_dinv[r0], w1 = g_dinv[r1], w2 = g_dinv[r2], w3 = g_dinv[r3];
        float4 v0 = *(const float4*)(H + (size_t)r0 * COLS + l * 4);
        float4 v1 = *(const float4*)(H + (size_t)r1 * COLS + l * 4);
        float4 v2 = *(const float4*)(H + (size_t)r2 * COLS + l * 4);
        float4 v3 = *(const float4*)(H + (size_t)r3 * COLS + l * 4);
        acc.x = fmaf(w0, v0.x, acc.x); acc.y = fmaf(w0, v0.y, acc.y);
        acc.z = fmaf(w0, v0.z, acc.z); acc.w = fmaf(w0, v0.w, acc.w);
        acc.x = fmaf(w1, v1.x, acc.x); acc.y = fmaf(w1, v1.y, acc.y);
        acc.z = fmaf(w1, v1.z, acc.z); acc.w = fmaf(w1, v1.w, acc.w);
        acc.x = fmaf(w2, v2.x, acc.x); acc.y = fmaf(w2, v2.y, acc.y);
        acc.z = fmaf(w2, v2.z, acc.z); acc.w = fmaf(w2, v2.w, acc.w);
        acc.x = fmaf(w3, v3.x, acc.x); acc.y = fmaf(w3, v3.y, acc.y);
        acc.z = fmaf(w3, v3.z, acc.z); acc.w = fmaf(w3, v3.w, acc.w);
    }
    for (; e < n; e++) {
        int r = nbr[e];
        float w = g_dinv[r];
        float4 hv = *(const float4*)(H + (size_t)r * COLS + l * 4);
        acc.x = fmaf(w, hv.x, acc.x); acc.y = fmaf(w, hv.y, acc.y);
        acc.z = fmaf(w, hv.z, acc.z); acc.w = fmaf(w, hv.w, acc.w);
    }

    // fused epilogue: self-loop + bias (+ relu)
    float dv = g_dinv[v];
    float d2 = dv * dv;
    float4 hv = *(const float4*)(H + (size_t)v * COLS + l * 4);
    float4 bv = *(const float4*)(bias + l * 4);
    float4 o;
    o.x = fmaf(dv, acc.x, fmaf(d2, hv.x, bv.x));
    o.y = fmaf(dv, acc.y, fmaf(d2, hv.y, bv.y));
    o.z = fmaf(dv, acc.z, fmaf(d2, hv.z, bv.z));
    o.w = fmaf(dv, acc.w, fmaf(d2, hv.w, bv.w));
    if (RELU) {
        o.x = fmaxf(o.x, 0.f); o.y = fmaxf(o.y, 0.f);
        o.z = fmaxf(o.z, 0.f); o.w = fmaxf(o.w, 0.f);
    }
    *(float4*)(dst + (size_t)v * COLS + l * 4) = o;
}

// ---------------------------------------------------------------------------
// launch
// ---------------------------------------------------------------------------
extern "C" void kernel_launch(void* const* d_in, const int* in_sizes, int n_in,
                              void* d_out, int out_size) {
    const float* x  = (const float*)d_in[0];
    const int*   ei = (const int*)d_in[1];      // int32 (JAX x64 disabled)
    const float* W1 = (const float*)d_in[2];
    const float* b1 = (const float*)d_in[3];
    const float* W2 = (const float*)d_in[4];
    const float* b2 = (const float*)d_in[5];
    float*       out = (float*)d_out;

    const int E = in_sizes[1] / 2;
    const int* rowp = ei;        // edge_index[0]
    const int* colp = ei + E;    // edge_index[1]

    float *H, *H1R, *H2;
    int *cnt, *fill;
    cudaGetSymbolAddress((void**)&H,    g_H);
    cudaGetSymbolAddress((void**)&H1R,  g_H1R);
    cudaGetSymbolAddress((void**)&H2,   g_H2);
    cudaGetSymbolAddress((void**)&cnt,  g_cnt);
    cudaGetSymbolAddress((void**)&fill, g_fill);

    // 1. CSR build: counts, dinv, offsets (scan), fill
    cudaMemsetAsync(cnt,  0, N_NODES * sizeof(int));
    cudaMemsetAsync(fill, 0, N_NODES * sizeof(int));
    count_kernel<<<(E + 255) / 256, 256>>>(colp, E);
    dinv_kernel<<<NB, 256>>>();
    block_sums_kernel<<<NB, 256>>>();
    scan_bsums_kernel<<<1, 512>>>();
    scan_block_kernel<<<NB, 256>>>();
    fill_csr_kernel<<<(E + 255) / 256, 256>>>(rowp, colp, E);

    // 2. layer 1 GEMM: H = x @ W1
    gemm_kernel<HID_C><<<(N_NODES + 127) / 128, 256>>>(x, W1, H, N_NODES);

    // 3. layer 1 gather + self-loop + bias + relu -> H1R
    gather_kernel<HID_C, true><<<(N_NODES * 32 + 255) / 256 + 1, 256>>>(H, b1, H1R);

    // 4. layer 2 GEMM: H2 = H1R @ W2
    gemm_kernel<OUT_C><<<(N_NODES + 127) / 128, 256>>>(H1R, W2, H2, N_NODES);

    // 5. layer 2 gather + self-loop + bias -> out (2 nodes per warp)
    gather_kernel<OUT_C, false><<<(N_NODES / 2 * 32 + 255) / 256 + 1, 256>>>(H2, b2, out);
}

// round 14
// speedup vs baseline: 3.9739x; 1.0969x over previous
#include <cuda_runtime.h>

#define N_NODES 100000
#define IN_C 128
#define HID_C 128
#define OUT_C 64
#define MAX_E 1600000
#define NB ((N_NODES + 255) / 256)

// Scratch (device globals: no allocation allowed in kernel_launch)
__device__ int   g_cnt [N_NODES];    // in-degree (by col)
__device__ int   g_fill[N_NODES];    // bucket fill cursors
__device__ int   g_off [N_NODES];    // CSR offsets (exclusive scan of cnt)
__device__ int   g_bsum[NB];         // per-block sums for scan
__device__ int   g_csr [MAX_E];      // CSR: source node (row) per edge, bucketed by col
__device__ float g_dinv[N_NODES];
__device__ float g_H  [(size_t)N_NODES * HID_C];   // layer-1 pre-agg h = xW1
__device__ float g_H1R[(size_t)N_NODES * HID_C];   // layer-1 output after agg+relu
__device__ float g_H2 [(size_t)N_NODES * OUT_C];   // layer-2 pre-agg h2 = h1R W2

// ---------------------------------------------------------------------------
// CSR construction
// ---------------------------------------------------------------------------
__global__ void count_kernel(const int* __restrict__ col, int E) {
    int i = blockIdx.x * blockDim.x + threadIdx.x;
    if (i < E) {
        asm volatile("red.global.add.s32 [%0], %1;"
                     :: "l"(&g_cnt[col[i]]), "r"(1) : "memory");
    }
}

__global__ void dinv_kernel() {
    int v = blockIdx.x * blockDim.x + threadIdx.x;
    if (v < N_NODES) {
        g_dinv[v] = rsqrtf((float)g_cnt[v] + 1.0f);
    }
}

__global__ void block_sums_kernel() {
    __shared__ int sh[256];
    int v = blockIdx.x * 256 + threadIdx.x;
    sh[threadIdx.x] = (v < N_NODES) ? g_cnt[v] : 0;
    __syncthreads();
#pragma unroll
    for (int d = 128; d > 0; d >>= 1) {
        if (threadIdx.x < d) sh[threadIdx.x] += sh[threadIdx.x + d];
        __syncthreads();
    }
    if (threadIdx.x == 0) g_bsum[blockIdx.x] = sh[0];
}

// Parallel exclusive scan of the NB (=391) block sums, single 512-thread block.
__global__ void scan_bsums_kernel() {
    __shared__ int sh[512];
    int t = threadIdx.x;
    int x = (t < NB) ? g_bsum[t] : 0;
    sh[t] = x;
    __syncthreads();
#pragma unroll
    for (int d = 1; d < 512; d <<= 1) {
        int y = (t >= d) ? sh[t - d] : 0;
        __syncthreads();
        sh[t] += y;
        __syncthreads();
    }
    if (t < NB) g_bsum[t] = sh[t] - x;   // exclusive
}

__global__ void scan_block_kernel() {
    __shared__ int sh[256];
    int v = blockIdx.x * 256 + threadIdx.x;
    int x = (v < N_NODES) ? g_cnt[v] : 0;
    sh[threadIdx.x] = x;
    __syncthreads();
#pragma unroll
    for (int d = 1; d < 256; d <<= 1) {
        int t = (threadIdx.x >= d) ? sh[threadIdx.x - d] : 0;
        __syncthreads();
        sh[threadIdx.x] += t;
        __syncthreads();
    }
    if (v < N_NODES) g_off[v] = g_bsum[blockIdx.x] + sh[threadIdx.x] - x;
}

__global__ void fill_csr_kernel(const int* __restrict__ rowp,
                                const int* __restrict__ colp, int E) {
    int i = blockIdx.x * blockDim.x + threadIdx.x;
    if (i < E) {
        int c = colp[i];
        int p = g_off[c] + atomicAdd(&g_fill[c], 1);
        g_csr[p] = rowp[i];
    }
}

// ---------------------------------------------------------------------------
// SGEMM: H = A @ W.  A [M,128] row-major, W [128,BN] row-major.
// BM=128, BK=16, 256 threads (16x16), TM=8, TN=BN/16.
// As padded to BM+4=132: 528B row stride keeps LDS.128 16B-aligned.
// ---------------------------------------------------------------------------
template <int BN>
__global__ void gemm_kernel(const float* __restrict__ A,
                            const float* __restrict__ W,
                            float* __restrict__ H,
                            int M) {
    constexpr int BM = 128;
    constexpr int BK = 16;
    constexpr int TM = 8;
    constexpr int TN = BN / 16;

    __shared__ float As[BK][BM + 4];
    __shared__ float Bs[BK][BN];

    const int tid = threadIdx.x;
    const int tx = tid % 16;
    const int ty = tid / 16;
    const int row0 = blockIdx.x * BM;

    float acc[TM][TN];
#pragma unroll
    for (int i = 0; i < TM; i++)
#pragma unroll
        for (int j = 0; j < TN; j++) acc[i][j] = 0.0f;

    for (int k0 = 0; k0 < 128; k0 += BK) {
        // A tile: 128x16 = 512 float4s, 2 per thread, stored transposed
#pragma unroll
        for (int i = 0; i < 2; i++) {
            int f = tid + i * 256;
            int r  = f >> 2;             // 0..127
            int k4 = (f & 3) * 4;        // 0,4,8,12
            float4 av = make_float4(0.f, 0.f, 0.f, 0.f);
            if (row0 + r < M) {
                av = *(const float4*)(A + (size_t)(row0 + r) * 128 + k0 + k4);
            }
            As[k4 + 0][r] = av.x;
            As[k4 + 1][r] = av.y;
            As[k4 + 2][r] = av.z;
            As[k4 + 3][r] = av.w;
        }

        // B tile: BK x BN
        constexpr int BF4 = BK * BN / 4;
#pragma unroll
        for (int f = tid; f < BF4; f += 256) {
            int bk = f / (BN / 4);
            int bc = f % (BN / 4);
            ((float4*)Bs[bk])[bc] =
                *(const float4*)(W + (size_t)(k0 + bk) * BN + bc * 4);
        }
        __syncthreads();

#pragma unroll
        for (int k = 0; k < BK; k++) {
            float a[TM], b[TN];
#pragma unroll
            for (int i = 0; i < TM; i += 4) {
                float4 av = *(const float4*)&As[k][ty * TM + i];
                a[i + 0] = av.x; a[i + 1] = av.y; a[i + 2] = av.z; a[i + 3] = av.w;
            }
#pragma unroll
            for (int j = 0; j < TN; j += 4) {
                float4 bv = ((const float4*)Bs[k])[(tx * TN + j) / 4];
                b[j + 0] = bv.x; b[j + 1] = bv.y; b[j + 2] = bv.z; b[j + 3] = bv.w;
            }
#pragma unroll
            for (int i = 0; i < TM; i++)
#pragma unroll
                for (int j = 0; j < TN; j++)
                    acc[i][j] = fmaf(a[i], b[j], acc[i][j]);
        }
        __syncthreads();
    }

#pragma unroll
    for (int i = 0; i < TM; i++) {
        int r = row0 + ty * TM + i;
        if (r < M) {
#pragma unroll
            for (int j = 0; j < TN; j += 4) {
                float4 o = make_float4(acc[i][j], acc[i][j + 1],
                                       acc[i][j + 2], acc[i][j + 3]);
                *(float4*)(H + (size_t)r * BN + tx * TN + j) = o;
            }
        }
    }
}

// ---------------------------------------------------------------------------
// CSR gather with fused GCN epilogue:
//   dst[v] = act( dinv[v] * sum_{r in nbr(v)} dinv[r]*H[r]
//                 + dinv[v]^2 * H[v] + bias )
// One (sub-)warp per node, lane handles one float4. 8 rows in flight (MLP).
// ---------------------------------------------------------------------------
template <int COLS, bool RELU>
__global__ void gather_kernel(const float* __restrict__ H,
                              const float* __restrict__ bias,
                              float* __restrict__ dst) {
    constexpr int LPE = COLS / 4;     // lanes per node (32 or 16)
    constexpr int NPW = 32 / LPE;     // nodes per warp (1 or 2)

    const int lane = threadIdx.x & 31;
    const int warp = (blockIdx.x * blockDim.x + threadIdx.x) >> 5;
    const int sub = lane / LPE;
    const int l   = lane % LPE;

    const int v = warp * NPW + sub;
    if (v >= N_NODES) return;

    const int beg = g_off[v];
    const int n   = g_cnt[v];
    const int* __restrict__ nbr = g_csr + beg;

    float4 acc = make_float4(0.f, 0.f, 0.f, 0.f);

    int e = 0;
    for (; e + 8 <= n; e += 8) {
        int   r0 = nbr[e + 0], r1 = nbr[e + 1], r2 = nbr[e + 2], r3 = nbr[e + 3];
        int   r4 = nbr[e + 4], r5 = nbr[e + 5], r6 = nbr[e + 6], r7 = nbr[e + 7];
        float w0 = g_dinv[r0], w1 = g_dinv[r1], w2 = g_dinv[r2], w3 = g_dinv[r3];
        float w4 = g_dinv[r4], w5 = g_dinv[r5], w6 = g_dinv[r6], w7 = g_dinv[r7];
        float4 v0 = *(const float4*)(H + (size_t)r0 * COLS + l * 4);
        float4 v1 = *(const float4*)(H + (size_t)r1 * COLS + l * 4);
        float4 v2 = *(const float4*)(H + (size_t)r2 * COLS + l * 4);
        float4 v3 = *(const float4*)(H + (size_t)r3 * COLS + l * 4);
        float4 v4 = *(const float4*)(H + (size_t)r4 * COLS + l * 4);
        float4 v5 = *(const float4*)(H + (size_t)r5 * COLS + l * 4);
        float4 v6 = *(const float4*)(H + (size_t)r6 * COLS + l * 4);
        float4 v7 = *(const float4*)(H + (size_t)r7 * COLS + l * 4);
        acc.x = fmaf(w0, v0.x, acc.x); acc.y = fmaf(w0, v0.y, acc.y);
        acc.z = fmaf(w0, v0.z, acc.z); acc.w = fmaf(w0, v0.w, acc.w);
        acc.x = fmaf(w1, v1.x, acc.x); acc.y = fmaf(w1, v1.y, acc.y);
        acc.z = fmaf(w1, v1.z, acc.z); acc.w = fmaf(w1, v1.w, acc.w);
        acc.x = fmaf(w2, v2.x, acc.x); acc.y = fmaf(w2, v2.y, acc.y);
        acc.z = fmaf(w2, v2.z, acc.z); acc.w = fmaf(w2, v2.w, acc.w);
        acc.x = fmaf(w3, v3.x, acc.x); acc.y = fmaf(w3, v3.y, acc.y);
        acc.z = fmaf(w3, v3.z, acc.z); acc.w = fmaf(w3, v3.w, acc.w);
        acc.x = fmaf(w4, v4.x, acc.x); acc.y = fmaf(w4, v4.y, acc.y);
        acc.z = fmaf(w4, v4.z, acc.z); acc.w = fmaf(w4, v4.w, acc.w);
        acc.x = fmaf(w5, v5.x, acc.x); acc.y = fmaf(w5, v5.y, acc.y);
        acc.z = fmaf(w5, v5.z, acc.z); acc.w = fmaf(w5, v5.w, acc.w);
        acc.x = fmaf(w6, v6.x, acc.x); acc.y = fmaf(w6, v6.y, acc.y);
        acc.z = fmaf(w6, v6.z, acc.z); acc.w = fmaf(w6, v6.w, acc.w);
        acc.x = fmaf(w7, v7.x, acc.x); acc.y = fmaf(w7, v7.y, acc.y);
        acc.z = fmaf(w7, v7.z, acc.z); acc.w = fmaf(w7, v7.w, acc.w);
    }
    for (; e < n; e++) {
        int r = nbr[e];
        float w = g_dinv[r];
        float4 hv = *(const float4*)(H + (size_t)r * COLS + l * 4);
        acc.x = fmaf(w, hv.x, acc.x); acc.y = fmaf(w, hv.y, acc.y);
        acc.z = fmaf(w, hv.z, acc.z); acc.w = fmaf(w, hv.w, acc.w);
    }

    // fused epilogue: self-loop + bias (+ relu)
    float dv = g_dinv[v];
    float d2 = dv * dv;
    float4 hv = *(const float4*)(H + (size_t)v * COLS + l * 4);
    float4 bv = *(const float4*)(bias + l * 4);
    float4 o;
    o.x = fmaf(dv, acc.x, fmaf(d2, hv.x, bv.x));
    o.y = fmaf(dv, acc.y, fmaf(d2, hv.y, bv.y));
    o.z = fmaf(dv, acc.z, fmaf(d2, hv.z, bv.z));
    o.w = fmaf(dv, acc.w, fmaf(d2, hv.w, bv.w));
    if (RELU) {
        o.x = fmaxf(o.x, 0.f); o.y = fmaxf(o.y, 0.f);
        o.z = fmaxf(o.z, 0.f); o.w = fmaxf(o.w, 0.f);
    }
    *(float4*)(dst + (size_t)v * COLS + l * 4) = o;
}

// ---------------------------------------------------------------------------
// launch — CSR build forked onto a side stream, overlapped with GEMM1
// ---------------------------------------------------------------------------
extern "C" void kernel_launch(void* const* d_in, const int* in_sizes, int n_in,
                              void* d_out, int out_size) {
    const float* x  = (const float*)d_in[0];
    const int*   ei = (const int*)d_in[1];      // int32 (JAX x64 disabled)
    const float* W1 = (const float*)d_in[2];
    const float* b1 = (const float*)d_in[3];
    const float* W2 = (const float*)d_in[4];
    const float* b2 = (const float*)d_in[5];
    float*       out = (float*)d_out;

    const int E = in_sizes[1] / 2;
    const int* rowp = ei;        // edge_index[0]
    const int* colp = ei + E;    // edge_index[1]

    float *H, *H1R, *H2;
    int *cnt, *fill;
    cudaGetSymbolAddress((void**)&H,    g_H);
    cudaGetSymbolAddress((void**)&H1R,  g_H1R);
    cudaGetSymbolAddress((void**)&H2,   g_H2);
    cudaGetSymbolAddress((void**)&cnt,  g_cnt);
    cudaGetSymbolAddress((void**)&fill, g_fill);

    // Side stream + events (host resources, created once; work is identical
    // every call so determinism holds).
    static cudaStream_t s2 = nullptr;
    static cudaEvent_t ev_fork = nullptr, ev_join = nullptr;
    if (!s2) {
        cudaStreamCreateWithFlags(&s2, cudaStreamNonBlocking);
        cudaEventCreateWithFlags(&ev_fork, cudaEventDisableTiming);
        cudaEventCreateWithFlags(&ev_join, cudaEventDisableTiming);
    }

    // Fork: CSR build on s2, GEMM1 on the capture (default) stream.
    cudaEventRecord(ev_fork, 0);
    cudaStreamWaitEvent(s2, ev_fork, 0);

    // --- s2: CSR build (independent of W1) ---
    cudaMemsetAsync(cnt,  0, N_NODES * sizeof(int), s2);
    cudaMemsetAsync(fill, 0, N_NODES * sizeof(int), s2);
    count_kernel<<<(E + 255) / 256, 256, 0, s2>>>(colp, E);
    dinv_kernel<<<NB, 256, 0, s2>>>();
    block_sums_kernel<<<NB, 256, 0, s2>>>();
    scan_bsums_kernel<<<1, 512, 0, s2>>>();
    scan_block_kernel<<<NB, 256, 0, s2>>>();
    fill_csr_kernel<<<(E + 255) / 256, 256, 0, s2>>>(rowp, colp, E);
    cudaEventRecord(ev_join, s2);

    // --- default stream: layer 1 GEMM H = x @ W1 (independent of edges) ---
    gemm_kernel<HID_C><<<(N_NODES + 127) / 128, 256>>>(x, W1, H, N_NODES);

    // Join: gather needs both CSR and H.
    cudaStreamWaitEvent(0, ev_join, 0);

    // layer 1 gather + self-loop + bias + relu -> H1R
    gather_kernel<HID_C, true><<<(N_NODES * 32 + 255) / 256 + 1, 256>>>(H, b1, H1R);

    // layer 2 GEMM: H2 = H1R @ W2
    gemm_kernel<OUT_C><<<(N_NODES + 127) / 128, 256>>>(H1R, W2, H2, N_NODES);

    // layer 2 gather + self-loop + bias -> out (2 nodes per warp)
    gather_kernel<OUT_C, false><<<(N_NODES / 2 * 32 + 255) / 256 + 1, 256>>>(H2, b2, out);
}

// round 16
// speedup vs baseline: 4.2249x; 1.0632x over previous
#include <cuda_runtime.h>
#include <cuda_fp16.h>

#define N_NODES 100000
#define IN_C 128
#define HID_C 128
#define OUT_C 64
#define MAX_E 1600000
#define NB ((N_NODES + 255) / 256)

// Scratch (device globals: no allocation allowed in kernel_launch)
__device__ int    g_cnt [N_NODES];    // in-degree (by col)
__device__ int    g_fill[N_NODES];    // bucket fill cursors
__device__ int    g_off [N_NODES];    // CSR offsets (exclusive scan of cnt)
__device__ int    g_bsum[NB];         // per-block sums for scan
__device__ int    g_csr [MAX_E];      // CSR: source node per edge, bucketed by col
__device__ float  g_dinv[N_NODES];
__device__ __half g_Hh [(size_t)N_NODES * HID_C];  // layer-1 pre-agg h = xW1 (fp16)
__device__ float  g_H1R[(size_t)N_NODES * HID_C];  // layer-1 output after agg+relu (fp32)
__device__ __half g_H2h[(size_t)N_NODES * OUT_C];  // layer-2 pre-agg h2 = h1R W2 (fp16)

// ---------------------------------------------------------------------------
// CSR construction
// ---------------------------------------------------------------------------
__global__ void count_kernel(const int* __restrict__ col, int E) {
    int i = blockIdx.x * blockDim.x + threadIdx.x;
    if (i < E) {
        asm volatile("red.global.add.s32 [%0], %1;"
                     :: "l"(&g_cnt[col[i]]), "r"(1) : "memory");
    }
}

__global__ void dinv_kernel() {
    int v = blockIdx.x * blockDim.x + threadIdx.x;
    if (v < N_NODES) {
        g_dinv[v] = rsqrtf((float)g_cnt[v] + 1.0f);
    }
}

__global__ void block_sums_kernel() {
    __shared__ int sh[256];
    int v = blockIdx.x * 256 + threadIdx.x;
    sh[threadIdx.x] = (v < N_NODES) ? g_cnt[v] : 0;
    __syncthreads();
#pragma unroll
    for (int d = 128; d > 0; d >>= 1) {
        if (threadIdx.x < d) sh[threadIdx.x] += sh[threadIdx.x + d];
        __syncthreads();
    }
    if (threadIdx.x == 0) g_bsum[blockIdx.x] = sh[0];
}

// Parallel exclusive scan of the NB (=391) block sums, single 512-thread block.
__global__ void scan_bsums_kernel() {
    __shared__ int sh[512];
    int t = threadIdx.x;
    int x = (t < NB) ? g_bsum[t] : 0;
    sh[t] = x;
    __syncthreads();
#pragma unroll
    for (int d = 1; d < 512; d <<= 1) {
        int y = (t >= d) ? sh[t - d] : 0;
        __syncthreads();
        sh[t] += y;
        __syncthreads();
    }
    if (t < NB) g_bsum[t] = sh[t] - x;   // exclusive
}

__global__ void scan_block_kernel() {
    __shared__ int sh[256];
    int v = blockIdx.x * 256 + threadIdx.x;
    int x = (v < N_NODES) ? g_cnt[v] : 0;
    sh[threadIdx.x] = x;
    __syncthreads();
#pragma unroll
    for (int d = 1; d < 256; d <<= 1) {
        int t = (threadIdx.x >= d) ? sh[threadIdx.x - d] : 0;
        __syncthreads();
        sh[threadIdx.x] += t;
        __syncthreads();
    }
    if (v < N_NODES) g_off[v] = g_bsum[blockIdx.x] + sh[threadIdx.x] - x;
}

__global__ void fill_csr_kernel(const int* __restrict__ rowp,
                                const int* __restrict__ colp, int E) {
    int i = blockIdx.x * blockDim.x + threadIdx.x;
    if (i < E) {
        int c = colp[i];
        int p = g_off[c] + atomicAdd(&g_fill[c], 1);
        g_csr[p] = rowp[i];
    }
}

// ---------------------------------------------------------------------------
// SGEMM: H(fp16) = A(fp32) @ W(fp32).  Epilogue converts to half.
// BM=128, BK=16, 256 threads (16x16), TM=8, TN=BN/16.
// ---------------------------------------------------------------------------
template <int BN>
__global__ void gemm_h_kernel(const float* __restrict__ A,
                              const float* __restrict__ W,
                              __half* __restrict__ H,
                              int M) {
    constexpr int BM = 128;
    constexpr int BK = 16;
    constexpr int TM = 8;
    constexpr int TN = BN / 16;

    __shared__ float As[BK][BM + 4];
    __shared__ float Bs[BK][BN];

    const int tid = threadIdx.x;
    const int tx = tid % 16;
    const int ty = tid / 16;
    const int row0 = blockIdx.x * BM;

    float acc[TM][TN];
#pragma unroll
    for (int i = 0; i < TM; i++)
#pragma unroll
        for (int j = 0; j < TN; j++) acc[i][j] = 0.0f;

    for (int k0 = 0; k0 < 128; k0 += BK) {
#pragma unroll
        for (int i = 0; i < 2; i++) {
            int f = tid + i * 256;
            int r  = f >> 2;
            int k4 = (f & 3) * 4;
            float4 av = make_float4(0.f, 0.f, 0.f, 0.f);
            if (row0 + r < M) {
                av = *(const float4*)(A + (size_t)(row0 + r) * 128 + k0 + k4);
            }
            As[k4 + 0][r] = av.x;
            As[k4 + 1][r] = av.y;
            As[k4 + 2][r] = av.z;
            As[k4 + 3][r] = av.w;
        }

        constexpr int BF4 = BK * BN / 4;
#pragma unroll
        for (int f = tid; f < BF4; f += 256) {
            int bk = f / (BN / 4);
            int bc = f % (BN / 4);
            ((float4*)Bs[bk])[bc] =
                *(const float4*)(W + (size_t)(k0 + bk) * BN + bc * 4);
        }
        __syncthreads();

#pragma unroll
        for (int k = 0; k < BK; k++) {
            float a[TM], b[TN];
#pragma unroll
            for (int i = 0; i < TM; i += 4) {
                float4 av = *(const float4*)&As[k][ty * TM + i];
                a[i + 0] = av.x; a[i + 1] = av.y; a[i + 2] = av.z; a[i + 3] = av.w;
            }
#pragma unroll
            for (int j = 0; j < TN; j += 4) {
                float4 bv = ((const float4*)Bs[k])[(tx * TN + j) / 4];
                b[j + 0] = bv.x; b[j + 1] = bv.y; b[j + 2] = bv.z; b[j + 3] = bv.w;
            }
#pragma unroll
            for (int i = 0; i < TM; i++)
#pragma unroll
                for (int j = 0; j < TN; j++)
                    acc[i][j] = fmaf(a[i], b[j], acc[i][j]);
        }
        __syncthreads();
    }

    // epilogue: convert TN floats per row to half, vector store
#pragma unroll
    for (int i = 0; i < TM; i++) {
        int r = row0 + ty * TM + i;
        if (r < M) {
            __half2 hbuf[TN / 2];
#pragma unroll
            for (int j = 0; j < TN; j += 2) {
                hbuf[j / 2] = __floats2half2_rn(acc[i][j], acc[i][j + 1]);
            }
            // TN=8 -> 16B store; TN=4 -> 8B store
            if (TN == 8) {
                *(uint4*)(H + (size_t)r * BN + tx * TN) = *(uint4*)hbuf;
            } else {
                *(uint2*)(H + (size_t)r * BN + tx * TN) = *(uint2*)hbuf;
            }
        }
    }
}

// ---------------------------------------------------------------------------
// CSR gather over fp16 features with fused GCN epilogue (fp32 accumulate):
//   dst[v] = act( dinv[v] * sum_{r in nbr(v)} dinv[r]*H[r]
//                 + dinv[v]^2 * H[v] + bias )
// Lane covers 8 half columns (16B). LPE = COLS/8 lanes per node,
// NPW = 32/LPE nodes per warp. Unroll 4 -> 4*NPW rows in flight per warp.
// ---------------------------------------------------------------------------
__device__ __forceinline__ void h8_to_f(const uint4& raw, float* f) {
    const __half2* h2 = (const __half2*)&raw;
#pragma unroll
    for (int q = 0; q < 4; q++) {
        float2 t = __half22float2(h2[q]);
        f[q * 2 + 0] = t.x;
        f[q * 2 + 1] = t.y;
    }
}

template <int COLS, bool RELU>
__global__ void gather_h_kernel(const __half* __restrict__ H,
                                const float* __restrict__ bias,
                                float* __restrict__ dst) {
    constexpr int LPE = COLS / 8;     // lanes per node (16 or 8)
    constexpr int NPW = 32 / LPE;     // nodes per warp (2 or 4)

    const int lane = threadIdx.x & 31;
    const int warp = (blockIdx.x * blockDim.x + threadIdx.x) >> 5;
    const int sub = lane / LPE;
    const int l   = lane % LPE;

    const int v = warp * NPW + sub;
    if (v >= N_NODES) return;

    const int beg = g_off[v];
    const int n   = g_cnt[v];
    const int* __restrict__ nbr = g_csr + beg;

    float acc[8];
#pragma unroll
    for (int j = 0; j < 8; j++) acc[j] = 0.0f;

    int e = 0;
    for (; e + 4 <= n; e += 4) {
        int   r0 = nbr[e + 0], r1 = nbr[e + 1], r2 = nbr[e + 2], r3 = nbr[e + 3];
        float w0 = g_dinv[r0], w1 = g_dinv[r1], w2 = g_dinv[r2], w3 = g_dinv[r3];
        uint4 q0 = *((const uint4*)(H + (size_t)r0 * COLS) + l);
        uint4 q1 = *((const uint4*)(H + (size_t)r1 * COLS) + l);
        uint4 q2 = *((const uint4*)(H + (size_t)r2 * COLS) + l);
        uint4 q3 = *((const uint4*)(H + (size_t)r3 * COLS) + l);
        float f0[8], f1[8], f2[8], f3[8];
        h8_to_f(q0, f0); h8_to_f(q1, f1); h8_to_f(q2, f2); h8_to_f(q3, f3);
#pragma unroll
        for (int j = 0; j < 8; j++) {
            acc[j] = fmaf(w0, f0[j], acc[j]);
            acc[j] = fmaf(w1, f1[j], acc[j]);
            acc[j] = fmaf(w2, f2[j], acc[j]);
            acc[j] = fmaf(w3, f3[j], acc[j]);
        }
    }
    for (; e < n; e++) {
        int r = nbr[e];
        float w = g_dinv[r];
        uint4 q = *((const uint4*)(H + (size_t)r * COLS) + l);
        float f[8];
        h8_to_f(q, f);
#pragma unroll
        for (int j = 0; j < 8; j++) acc[j] = fmaf(w, f[j], acc[j]);
    }

    // fused epilogue: self-loop + bias (+ relu)
    float dv = g_dinv[v];
    float d2 = dv * dv;
    uint4 qv = *((const uint4*)(H + (size_t)v * COLS) + l);
    float hv[8];
    h8_to_f(qv, hv);
    float4 b0 = *((const float4*)(bias + l * 8));
    float4 b1 = *((const float4*)(bias + l * 8) + 1);
    float bv[8] = {b0.x, b0.y, b0.z, b0.w, b1.x, b1.y, b1.z, b1.w};

    float o[8];
#pragma unroll
    for (int j = 0; j < 8; j++) {
        o[j] = fmaf(dv, acc[j], fmaf(d2, hv[j], bv[j]));
        if (RELU) o[j] = fmaxf(o[j], 0.f);
    }
    float* dp = dst + (size_t)v * COLS + l * 8;
    *(float4*)(dp)     = make_float4(o[0], o[1], o[2], o[3]);
    *(float4*)(dp + 4) = make_float4(o[4], o[5], o[6], o[7]);
}

// ---------------------------------------------------------------------------
// launch — CSR build forked onto a side stream, overlapped with GEMM1
// ---------------------------------------------------------------------------
extern "C" void kernel_launch(void* const* d_in, const int* in_sizes, int n_in,
                              void* d_out, int out_size) {
    const float* x  = (const float*)d_in[0];
    const int*   ei = (const int*)d_in[1];      // int32 (JAX x64 disabled)
    const float* W1 = (const float*)d_in[2];
    const float* b1 = (const float*)d_in[3];
    const float* W2 = (const float*)d_in[4];
    const float* b2 = (const float*)d_in[5];
    float*       out = (float*)d_out;

    const int E = in_sizes[1] / 2;
    const int* rowp = ei;        // edge_index[0]
    const int* colp = ei + E;    // edge_index[1]

    __half *Hh, *H2h;
    float *H1R;
    int *cnt, *fill;
    cudaGetSymbolAddress((void**)&Hh,   g_Hh);
    cudaGetSymbolAddress((void**)&H2h,  g_H2h);
    cudaGetSymbolAddress((void**)&H1R,  g_H1R);
    cudaGetSymbolAddress((void**)&cnt,  g_cnt);
    cudaGetSymbolAddress((void**)&fill, g_fill);

    static cudaStream_t s2 = nullptr;
    static cudaEvent_t ev_fork = nullptr, ev_join = nullptr;
    if (!s2) {
        cudaStreamCreateWithFlags(&s2, cudaStreamNonBlocking);
        cudaEventCreateWithFlags(&ev_fork, cudaEventDisableTiming);
        cudaEventCreateWithFlags(&ev_join, cudaEventDisableTiming);
    }

    // Fork: CSR build on s2, GEMM1 on the capture (default) stream.
    cudaEventRecord(ev_fork, 0);
    cudaStreamWaitEvent(s2, ev_fork, 0);

    // --- s2: CSR build (independent of W1) ---
    cudaMemsetAsync(cnt,  0, N_NODES * sizeof(int), s2);
    cudaMemsetAsync(fill, 0, N_NODES * sizeof(int), s2);
    count_kernel<<<(E + 255) / 256, 256, 0, s2>>>(colp, E);
    dinv_kernel<<<NB, 256, 0, s2>>>();
    block_sums_kernel<<<NB, 256, 0, s2>>>();
    scan_bsums_kernel<<<1, 512, 0, s2>>>();
    scan_block_kernel<<<NB, 256, 0, s2>>>();
    fill_csr_kernel<<<(E + 255) / 256, 256, 0, s2>>>(rowp, colp, E);
    cudaEventRecord(ev_join, s2);

    // --- default stream: layer 1 GEMM H = x @ W1 (fp16 out) ---
    gemm_h_kernel<HID_C><<<(N_NODES + 127) / 128, 256>>>(x, W1, Hh, N_NODES);

    // Join: gather needs both CSR and H.
    cudaStreamWaitEvent(0, ev_join, 0);

    // layer 1 gather + self-loop + bias + relu -> H1R (fp32); 2 nodes/warp
    gather_h_kernel<HID_C, true>
        <<<((N_NODES + 1) / 2 * 32 + 255) / 256 + 1, 256>>>(Hh, b1, H1R);

    // layer 2 GEMM: H2 = H1R @ W2 (fp16 out)
    gemm_h_kernel<OUT_C><<<(N_NODES + 127) / 128, 256>>>(H1R, W2, H2h, N_NODES);

    // layer 2 gather + self-loop + bias -> out (fp32); 4 nodes/warp
    gather_h_kernel<OUT_C, false>
        <<<((N_NODES + 3) / 4 * 32 + 255) / 256 + 1, 256>>>(H2h, b2, out);
}